// round 3
// baseline (speedup 1.0000x reference)
#include <cuda_runtime.h>
#include <cstdint>

#define NFEAT 20000
#define DOUT  256
#define BATCH 4096
#define KD    64

// ---------------- scratch (static device globals; no runtime allocation) ----
__device__ float g_Z[(size_t)DOUT * NFEAT];        // zpre[d][n] = log(10*clip(al))
__device__ float g_cand_val[DOUT * 256];           // per-row top-256 log-softmax values (desc)
__device__ int   g_cand_idx[DOUT * 256];           // matching column indices
__device__ int   g_sel[DOUT];                      // selected column per output row d

// orderable-uint mapping for floats (monotone increasing)
__device__ __forceinline__ uint32_t f2o(float f) {
    uint32_t b = __float_as_uint(f);
    return (b & 0x80000000u) ? ~b : (b | 0x80000000u);
}
__device__ __forceinline__ float o2f(uint32_t m) {
    uint32_t b = (m & 0x80000000u) ? (m & 0x7fffffffu) : ~m;
    return __uint_as_float(b);
}

// ---------------------------------------------------------------------------
// K1: M = u @ tinyW  (20000x256, K=64), softmax over the 256 axis per feature n,
//     zpre = ln(10) + clamp(log-softmax, ln(EPS), ln(0.9999999)).
//     One warp handles 4 features (n); lane holds d = lane + 32*j, j<8.
//     smem tile [32 n][257] transposes for coalesced writes of Z[d][n].
// ---------------------------------------------------------------------------
__global__ void __launch_bounds__(256) k1_gemm(const float* __restrict__ u,
                                               const float* __restrict__ tinyW) {
    __shared__ float zs[32 * 257];   // 32.9 KB, stride 257 => conflict-free
    const int t = threadIdx.x, lane = t & 31, w = t >> 5;
    const int n0 = blockIdx.x * 32;
    const int nb = n0 + w * 4;

    float acc[8][4];
#pragma unroll
    for (int j = 0; j < 8; j++)
#pragma unroll
        for (int i = 0; i < 4; i++) acc[j][i] = 0.f;

#pragma unroll 4
    for (int k = 0; k < KD; k += 4) {
        float4 uv[4];
#pragma unroll
        for (int i = 0; i < 4; i++)
            uv[i] = *reinterpret_cast<const float4*>(u + (size_t)(nb + i) * KD + k);
#pragma unroll
        for (int kk = 0; kk < 4; kk++) {
            float wreg[8];
#pragma unroll
            for (int j = 0; j < 8; j++)
                wreg[j] = __ldg(tinyW + (k + kk) * DOUT + lane + 32 * j);
#pragma unroll
            for (int i = 0; i < 4; i++) {
                float uk = (kk == 0) ? uv[i].x : (kk == 1) ? uv[i].y
                         : (kk == 2) ? uv[i].z : uv[i].w;
#pragma unroll
                for (int j = 0; j < 8; j++) acc[j][i] = fmaf(uk, wreg[j], acc[j][i]);
            }
        }
    }

    const float LN10  = 2.302585092994046f;
    const float LNEPS = -16.11809565095832f;       // ln(1e-7)
    const float LNHI  = -1.0000000500000026e-7f;   // ln(0.9999999)
#pragma unroll
    for (int i = 0; i < 4; i++) {
        float m = acc[0][i];
#pragma unroll
        for (int j = 1; j < 8; j++) m = fmaxf(m, acc[j][i]);
#pragma unroll
        for (int o = 16; o; o >>= 1) m = fmaxf(m, __shfl_xor_sync(0xffffffffu, m, o));
        float s = 0.f;
#pragma unroll
        for (int j = 0; j < 8; j++) s += expf(acc[j][i] - m);
#pragma unroll
        for (int o = 16; o; o >>= 1) s += __shfl_xor_sync(0xffffffffu, s, o);
        float lns = logf(s);
#pragma unroll
        for (int j = 0; j < 8; j++) {
            float lal = acc[j][i] - m - lns;                // log softmax
            lal = fminf(fmaxf(lal, LNEPS), LNHI);           // == log(clip(al))
            zs[(w * 4 + i) * 257 + lane + 32 * j] = LN10 + lal;
        }
    }
    __syncthreads();
    // coalesced transpose-out: warp lanes sweep n, rows sweep d
    const int tx = t & 31, ty = t >> 5;
    for (int dd = ty; dd < DOUT; dd += 8)
        g_Z[(size_t)dd * NFEAT + n0 + tx] = zs[tx * 257 + dd];
}

// ---------------------------------------------------------------------------
// K3: one CTA per output row d. Build z = (zpre + gumbel)/temp in registers,
//     compute c_d = rowmax + log(sum exp), binary-search the top-256 threshold
//     on orderable uints, collect, bitonic-sort (value desc, index asc).
// ---------------------------------------------------------------------------
__global__ void __launch_bounds__(512) k3_select(const float* __restrict__ uniform) {
    const int d = blockIdx.x;
    const int t = threadIdx.x, lane = t & 31, w = t >> 5;
    __shared__ uint32_t shu[16];
    __shared__ float    shf[16];
    __shared__ int      shi[16];
    __shared__ unsigned long long skey[512];
    __shared__ int s_cnt;

    const float temp = fmaxf(0.1f, 10.0f * 0.99999f);
    uint32_t mv[40];
    uint32_t mmax = 0;
#pragma unroll
    for (int i = 0; i < 40; i++) {
        int n = i * 512 + t;
        uint32_t m = 0;
        if (n < NFEAT) {
            float zp  = g_Z[(size_t)d * NFEAT + n];
            float uu  = uniform[(size_t)d * NFEAT + n];
            float gum = -logf(-logf(uu));
            float v   = (zp + gum) / temp;
            m = f2o(v);                               // finite => m >= 1
        }
        mv[i] = m;
        mmax = max(mmax, m);
    }
    // block max (mapped domain == float max)
#pragma unroll
    for (int o = 16; o; o >>= 1) mmax = max(mmax, __shfl_xor_sync(0xffffffffu, mmax, o));
    if (lane == 0) shu[w] = mmax;
    __syncthreads();
    uint32_t rmax_m = shu[0];
#pragma unroll
    for (int i = 1; i < 16; i++) rmax_m = max(rmax_m, shu[i]);
    const float rowmax = o2f(rmax_m);

    // sum of exp(z - rowmax)
    float ls = 0.f;
#pragma unroll
    for (int i = 0; i < 40; i++)
        if (mv[i]) ls += expf(o2f(mv[i]) - rowmax);
#pragma unroll
    for (int o = 16; o; o >>= 1) ls += __shfl_xor_sync(0xffffffffu, ls, o);
    if (lane == 0) shf[w] = ls;
    __syncthreads();
    float ssum = 0.f;
#pragma unroll
    for (int i = 0; i < 16; i++) ssum += shf[i];
    const float c = rowmax + logf(ssum);              // log-sum-exp offset

    // binary search: largest thr with count(mv >= thr) >= 256
    uint32_t lo = 0, hi = rmax_m;
    while (lo < hi) {
        uint32_t mid = lo + ((hi - lo) >> 1) + 1u;    // >= 1, so padding(0) excluded
        int cl = 0;
#pragma unroll
        for (int i = 0; i < 40; i++) cl += (mv[i] >= mid) ? 1 : 0;
#pragma unroll
        for (int o = 16; o; o >>= 1) cl += __shfl_xor_sync(0xffffffffu, cl, o);
        __syncthreads();                              // protect shi reuse
        if (lane == 0) shi[w] = cl;
        __syncthreads();
        int cnt = 0;
#pragma unroll
        for (int i = 0; i < 16; i++) cnt += shi[i];
        if (cnt >= 256) lo = mid; else hi = mid - 1;
    }

    if (t == 0) s_cnt = 0;
    __syncthreads();
    const uint32_t thr = lo;
#pragma unroll
    for (int i = 0; i < 40; i++)
        if (mv[i] >= thr) {
            int n = i * 512 + t;
            int p = atomicAdd(&s_cnt, 1);
            if (p < 512)
                skey[p] = ((unsigned long long)mv[i] << 32) | (uint32_t)(NFEAT - n);
        }
    __syncthreads();
    int cnt = s_cnt; if (cnt > 512) cnt = 512;
    if (t >= cnt) skey[t] = 0ull;
    __syncthreads();

    // bitonic sort ascending on 64-bit key (value, NFEAT-idx) => top has desc val, asc idx
    for (int k = 2; k <= 512; k <<= 1)
        for (int j = k >> 1; j > 0; j >>= 1) {
            int ixj = t ^ j;
            if (ixj > t) {
                unsigned long long a = skey[t], b = skey[ixj];
                if ((a > b) == ((t & k) == 0)) { skey[t] = b; skey[ixj] = a; }
            }
            __syncthreads();
        }

    if (t < 256) {
        unsigned long long kk = skey[511 - t];        // t-th largest
        g_cand_val[d * 256 + t] = o2f((uint32_t)(kk >> 32)) - c;   // log softmax value
        g_cand_idx[d * 256 + t] = NFEAT - (int)(kk & 0xffffffffu);
    }
}

// ---------------------------------------------------------------------------
// K4: greedy assignment on 256 rows x top-256 candidates. Single CTA,
//     thread t owns row t. Tie-break: larger value, then smaller row, then
//     (within a row) smaller column (lists already sorted that way).
// ---------------------------------------------------------------------------
__global__ void __launch_bounds__(256) k4_greedy() {
    __shared__ float cval[256];
    __shared__ int   ccol[256];
    __shared__ int   cptr[256];
    __shared__ uint32_t used[(NFEAT + 31) / 32];      // 625 words
    __shared__ unsigned long long wmax[8];
    const int t = threadIdx.x, lane = t & 31, w = t >> 5;
    const float NEGINF = __int_as_float(0xff800000);

    for (int i = t; i < (NFEAT + 31) / 32; i += 256) used[i] = 0u;
    cval[t] = __ldg(&g_cand_val[t * 256]);
    ccol[t] = __ldg(&g_cand_idx[t * 256]);
    cptr[t] = 0;
    __syncthreads();

    for (int step = 0; step < 256; step++) {
        unsigned long long key =
            ((unsigned long long)f2o(cval[t]) << 32) | (uint32_t)(255 - t);
#pragma unroll
        for (int o = 16; o; o >>= 1) {
            unsigned long long ok = __shfl_xor_sync(0xffffffffu, key, o);
            if (ok > key) key = ok;
        }
        if (lane == 0) wmax[w] = key;
        __syncthreads();
        if (t == 0) {
            unsigned long long best = wmax[0];
#pragma unroll
            for (int i = 1; i < 8; i++) if (wmax[i] > best) best = wmax[i];
            int x = 255 - (int)(best & 0xffffffffu);
            int y = ccol[x];
            g_sel[x] = y;
            cval[x] = NEGINF;
            used[y >> 5] |= (1u << (y & 31));
        }
        __syncthreads();
        if (cval[t] != NEGINF) {
            int cc = ccol[t];
            if ((used[cc >> 5] >> (cc & 31)) & 1u) {
                int p = cptr[t];
                do {
                    p++;
                    cc = __ldg(&g_cand_idx[t * 256 + p]);
                } while (p < 255 && ((used[cc >> 5] >> (cc & 31)) & 1u));
                cptr[t] = p; ccol[t] = cc;
                cval[t] = __ldg(&g_cand_val[t * 256 + p]);
            }
        }
        __syncthreads();
    }
}

// ---------------------------------------------------------------------------
// K5: Y[b,d] = X[b, sel[d]]  (dl rows are one-hot => matmul is a gather)
// ---------------------------------------------------------------------------
__global__ void __launch_bounds__(256) k5_gather(const float* __restrict__ X,
                                                 float* __restrict__ Y) {
    __shared__ int scol[256];
    const int b = blockIdx.x;
    scol[threadIdx.x] = g_sel[threadIdx.x];
    __syncthreads();
    Y[(size_t)b * DOUT + threadIdx.x] =
        __ldg(X + (size_t)b * NFEAT + scol[threadIdx.x]);
}

// ---------------------------------------------------------------------------
extern "C" void kernel_launch(void* const* d_in, const int* in_sizes, int n_in,
                              void* d_out, int out_size) {
    const float* X       = (const float*)d_in[0];   // (4096, 20000)
    const float* u       = (const float*)d_in[1];   // (20000, 64)
    const float* tinyW   = (const float*)d_in[2];   // (64, 256)
    const float* uniform = (const float*)d_in[3];   // (256, 20000)
    float* Y = (float*)d_out;                       // (4096, 256)

    k1_gemm  <<<NFEAT / 32, 256>>>(u, tinyW);
    k3_select<<<DOUT, 512>>>(uniform);
    k4_greedy<<<1, 256>>>();
    k5_gather<<<BATCH, 256>>>(X, Y);
}